// round 9
// baseline (speedup 1.0000x reference)
#include <cuda_runtime.h>

#define Nn 2
#define Cc 8
#define Hh 256
#define Ww 512
#define KK 9
#define PADW 4
#define BH 8
#define BW 32
#define TWX 16                 // threads along w, each covers 2 outputs
#define ROWS (BH + 8)          // 16
#define COLS (BW + 8)          // 40
#define NTHREADS (TWX * BH)    // 128

typedef unsigned long long u64;

__device__ __forceinline__ u64 pk(float lo, float hi) {
    u64 r;
    asm("mov.b64 %0, {%1, %2};" : "=l"(r) : "f"(lo), "f"(hi));
    return r;
}
__device__ __forceinline__ void unpk(u64 v, float& lo, float& hi) {
    asm("mov.b64 {%0, %1}, %2;" : "=f"(lo), "=f"(hi) : "l"(v));
}
// d = a*b + c, elementwise on packed f32x2 (Blackwell FFMA2)
__device__ __forceinline__ u64 fma2(u64 a, u64 b, u64 c) {
    u64 d;
    asm("fma.rn.f32x2 %0, %1, %2, %3;" : "=l"(d) : "l"(a), "l"(b), "l"(c));
    return d;
}

__global__ __launch_bounds__(NTHREADS, 6)
void dfl_kernel(const float* __restrict__ x,
                const float* __restrict__ filt,
                const float* __restrict__ bias,
                float* __restrict__ out)
{
    __shared__ __align__(16) float sx[Cc][ROWS][COLS];   // 20,480 B

    const int n  = blockIdx.z;
    const int h0 = blockIdx.y * BH;
    const int w0 = blockIdx.x * BW;
    const int tid = threadIdx.y * TWX + threadIdx.x;

    const int hl = threadIdx.y;          // 0..7
    const int h  = h0 + hl;
    const int wl = threadIdx.x * 2;      // local output col (even)
    const int w  = w0 + wl;

    const float* fbase = filt + ((size_t)n * (KK * KK) * Hh + h) * Ww + w;
    const size_t tap_stride = (size_t)Hh * Ww;

    // ---- kick off i=0 taps + bias early: overlap the x-fill below ----
    u64 f0[KK];
    #pragma unroll
    for (int j = 0; j < KK; j++)
        f0[j] = __ldcs(reinterpret_cast<const u64*>(fbase + (size_t)j * tap_stride));
    u64 b = *reinterpret_cast<const u64*>(bias + ((size_t)n * Hh + h) * Ww + w);

    // ---- fill shared x tile (zero-padded halo) ----
    const float* xn = x + (size_t)n * Cc * Hh * Ww;
    #pragma unroll
    for (int g = tid; g < Cc * ROWS * 10; g += NTHREADS) {
        int q  = g % 10;
        int rc = g / 10;
        int r  = rc % ROWS;
        int c  = rc / ROWS;
        int gh = h0 - PADW + r;
        int gw = w0 - PADW + q * 4;
        float4 v = make_float4(0.f, 0.f, 0.f, 0.f);
        if (gh >= 0 && gh < Hh) {
            const float* row = xn + ((size_t)c * Hh + gh) * Ww;
            if (gw >= 0 && gw + 3 < Ww) {
                v = *reinterpret_cast<const float4*>(row + gw);
            } else {
                float t0 = (gw + 0 >= 0 && gw + 0 < Ww) ? row[gw + 0] : 0.f;
                float t1 = (gw + 1 >= 0 && gw + 1 < Ww) ? row[gw + 1] : 0.f;
                float t2 = (gw + 2 >= 0 && gw + 2 < Ww) ? row[gw + 2] : 0.f;
                float t3 = (gw + 3 >= 0 && gw + 3 < Ww) ? row[gw + 3] : 0.f;
                v = make_float4(t0, t1, t2, t3);
            }
        }
        // COLS*4 = 160B row stride, q*16 byte offsets -> 16B aligned
        *reinterpret_cast<float4*>(&sx[c][r][q * 4]) = v;
    }

    u64 acc[Cc];
    #pragma unroll
    for (int c = 0; c < Cc; c++) acc[c] = b;

    __syncthreads();

    // ---- main loop: 9 FFMA2 per (i,c) instead of 18 FFMA ----
    for (int i = 0; i < KK; i++) {
        u64 f[KK];
        if (i == 0) {
            #pragma unroll
            for (int j = 0; j < KK; j++) f[j] = f0[j];
        } else {
            #pragma unroll
            for (int j = 0; j < KK; j++)
                f[j] = __ldcs(reinterpret_cast<const u64*>(
                          fbase + (size_t)(i * KK + j) * tap_stride));
        }

        #pragma unroll
        for (int c = 0; c < Cc; c++) {
            // 10-float window: 5 x LDS.64 (conflict-free), as packed pairs
            const u64* sp = reinterpret_cast<const u64*>(&sx[c][hl + i][wl]);
            u64 e0 = sp[0], e1 = sp[1], e2 = sp[2], e3 = sp[3], e4 = sp[4];
            float l0, h0f, l1, h1f, l2, h2f, l3, h3f, l4, h4f;
            unpk(e0, l0, h0f); unpk(e1, l1, h1f); unpk(e2, l2, h2f);
            unpk(e3, l3, h3f); unpk(e4, l4, h4f);
            u64 o0 = pk(h0f, l1);
            u64 o1 = pk(h1f, l2);
            u64 o2 = pk(h2f, l3);
            u64 o3 = pk(h3f, l4);

            // pair_j = (xw[j], xw[j+1]); acc += pair_j * (f.x, f.y)
            acc[c] = fma2(e0, f[0], acc[c]);
            acc[c] = fma2(o0, f[1], acc[c]);
            acc[c] = fma2(e1, f[2], acc[c]);
            acc[c] = fma2(o1, f[3], acc[c]);
            acc[c] = fma2(e2, f[4], acc[c]);
            acc[c] = fma2(o2, f[5], acc[c]);
            acc[c] = fma2(e3, f[6], acc[c]);
            acc[c] = fma2(o3, f[7], acc[c]);
            acc[c] = fma2(e4, f[8], acc[c]);
        }
    }

    // ---- store (evict-first) ----
    float* obase = out + (((size_t)n * Cc) * Hh + h) * Ww + w;
    #pragma unroll
    for (int c = 0; c < Cc; c++)
        __stcs(reinterpret_cast<u64*>(obase + (size_t)c * Hh * Ww), acc[c]);
}

extern "C" void kernel_launch(void* const* d_in, const int* in_sizes, int n_in,
                              void* d_out, int out_size)
{
    const float* x    = (const float*)d_in[0];   // x_in  (2,8,256,512)
    const float* filt = (const float*)d_in[1];   // filters (2,81,256,512)
    const float* bias = (const float*)d_in[2];   // filters_biases (2,1,256,512)
    float* out = (float*)d_out;

    dim3 grid(Ww / BW, Hh / BH, Nn);   // (16, 32, 2) = 1024 CTAs
    dim3 block(TWX, BH, 1);            // (16, 8)
    dfl_kernel<<<grid, block>>>(x, filt, bias, out);
}